// round 16
// baseline (speedup 1.0000x reference)
#include <cuda_runtime.h>
#include <cuda_bf16.h>
#include <math.h>

#define NN   8192
#define HH   256
#define DD   300
#define GXC  1024
#define KPX  320    // D padded to 64-multiple
#define GRID 296    // 2 CTAs/SM x 148 SMs; all co-resident (96KB smem, 128 regs)

// ---------------- scratch -----------------------------------------------------
__device__ __align__(256) float         g_gx [NN * GXC];
__device__ __align__(256) float         g_YH [NN * GXC];
__device__ __align__(256) float         g_C  [NN * HH];
__device__ __align__(256) __nv_bfloat16 g_Hh [NN * HH];    // bf16 split h
__device__ __align__(256) __nv_bfloat16 g_Hl [NN * HH];
__device__ __align__(256) __nv_bfloat16 g_Xh [NN * KPX];
__device__ __align__(256) __nv_bfloat16 g_Xl [NN * KPX];
__device__ __align__(256) __nv_bfloat16 g_WxBh[GXC * KPX];
__device__ __align__(256) __nv_bfloat16 g_WxBl[GXC * KPX];
__device__ __align__(256) __nv_bfloat16 g_WhBh[GXC * HH];
__device__ __align__(256) __nv_bfloat16 g_WhBl[GXC * HH];
__device__ __align__(256) float         g_WhT [HH * GXC];   // [j][m] for fused matvec
__device__ __align__(256) float         g_bias[GXC];

// software grid barrier state (monotonic generation; deterministic per replay)
__device__ unsigned g_bar_count = 0;
__device__ unsigned g_bar_gen   = 0;

__device__ __forceinline__ float sigf(float x) { return 1.0f / (1.0f + expf(-x)); }

__device__ __forceinline__ void split2(float v, __nv_bfloat16& h, __nv_bfloat16& l) {
    h = __float2bfloat16_rn(v);
    l = __float2bfloat16_rn(v - __bfloat162float(h));
}

// ---------------- generic-PTX tensor helpers ----------------------------------
__device__ __forceinline__ unsigned smem_u32(const void* p) {
    unsigned a;
    asm("{ .reg .u64 t; cvta.to.shared.u64 t, %1; cvt.u32.u64 %0, t; }"
        : "=r"(a) : "l"(p));
    return a;
}
__device__ __forceinline__ unsigned sw128(unsigned x) { return x ^ ((x >> 3) & 0x70); }

__device__ __forceinline__ void cpa16(unsigned d, const void* s) {
    asm volatile("cp.async.cg.shared.global [%0], [%1], 16;" :: "r"(d), "l"(s));
}
#define CP_COMMIT() asm volatile("cp.async.commit_group;" ::: "memory")
template <int N> __device__ __forceinline__ void cp_wait() {
    asm volatile("cp.async.wait_group %0;" :: "n"(N) : "memory");
}

__device__ __forceinline__ void ldsm4(unsigned* r, unsigned addr) {
    asm volatile("ldmatrix.sync.aligned.m8n8.x4.shared.b16 {%0,%1,%2,%3}, [%4];"
                 : "=r"(r[0]), "=r"(r[1]), "=r"(r[2]), "=r"(r[3]) : "r"(addr));
}

__device__ __forceinline__ void mma16816(float* c, const unsigned* a,
                                         unsigned b0, unsigned b1) {
    asm volatile(
        "mma.sync.aligned.m16n8k16.row.col.f32.bf16.bf16.f32 "
        "{%0,%1,%2,%3}, {%4,%5,%6,%7}, {%8,%9}, {%0,%1,%2,%3};"
        : "+f"(c[0]), "+f"(c[1]), "+f"(c[2]), "+f"(c[3])
        : "r"(a[0]), "r"(a[1]), "r"(a[2]), "r"(a[3]), "r"(b0), "r"(b1));
}

// ---------------- grid-wide software barrier (nanosleep backoff) --------------
// Safe: all GRID CTAs are co-resident. Backoff keeps the L2 poll pressure low
// (the r15 no-backoff spin serialized ~296 pollers on one LTS address and
// stole L2 bandwidth from still-computing CTAs).
__device__ __forceinline__ void gsync() {
    __syncthreads();
    if (threadIdx.x == 0) {
        unsigned gen = *((volatile unsigned*)&g_bar_gen);
        __threadfence();                       // release prior writes
        if (atomicAdd(&g_bar_count, 1u) == GRID - 1u) {
            g_bar_count = 0;
            __threadfence();                   // reset visible before gen bump
            atomicExch(&g_bar_gen, gen + 1u);  // release
        } else {
            unsigned ns = 256;
            while (*((volatile unsigned*)&g_bar_gen) == gen) {
                __nanosleep(ns);
                if (ns < 4096) ns <<= 1;
            }
        }
        __threadfence();                       // acquire
    }
    __syncthreads();
}

// ---------------- prep: weight pack + bias + embedding gather/split -----------
__global__ void prep_kernel(const float* __restrict__ Wx, const float* __restrict__ bx,
                            const float* __restrict__ Wh, const float* __restrict__ bh,
                            const int*   __restrict__ xs, const float* __restrict__ emb) {
    int b = blockIdx.x, t = threadIdx.x;
    if (b < 1280) {
        int i = b * 256 + t;
        if (i < GXC * KPX) {
            int m = i / KPX, k = i - m * KPX;
            float v = (k < DD) ? Wx[m * DD + k] : 0.0f;
            split2(v, g_WxBh[i], g_WxBl[i]);
        }
        if (i < GXC * HH) {
            float v = Wh[i];                       // i = m*256 + j (K-contig)
            split2(v, g_WhBh[i], g_WhBl[i]);
            int m = i >> 8, j = i & 255;
            g_WhT[j * GXC + m] = v;
        }
        if (i < GXC) g_bias[i] = bx[i] + bh[i];
    } else {
        int j = (b - 1280) * 256 + t;              // [0, NN*KPX)
        int n = j / KPX, k = j - n * KPX;
        float v = (k < DD) ? emb[(size_t)xs[n] * DD + k] : 0.0f;
        split2(v, g_Xh[j], g_Xl[j]);
    }
}

// ---------------- GEMM phase (persistent tiles, 3-stage cp.async) -------------
// MODE 0: g_gx = g_X @ g_WxB^T + bias   (K=320)
// MODE 1: g_YH[lo..] = bf16-split H[lo..] @ g_WhB^T (K=256)
// Split-bf16 3-pass via chunk segments: (Ah,Bh), (Al,Bh), (Ah,Bl).
// CTA_N fixed 128 (8 column tiles). Warp grid WM x WN.
template <int MODE, int CTA_M, int WM, int WN>
__device__ void gemm_phase(char* smem, int lo, int M, int ntiles) {
    constexpr int KEL = (MODE == 0) ? KPX : HH;
    constexpr int KC  = KEL / 64;
    constexpr int NCH = 3 * KC;
    constexpr int MW  = CTA_M / WM, NW = 128 / WN;
    constexpr int MF  = MW / 16,  NF = NW / 8, NF2 = NF / 2;
    constexpr int ALINES = CTA_M * 8;              // 16B lines per chunk
    constexpr int ITER   = (CTA_M + 128) * 8 / 256;
    constexpr unsigned SS = (unsigned)(CTA_M + 128) * 128u;  // stage bytes

    const __nv_bfloat16* Ah = (MODE == 0) ? g_Xh : (g_Hh + (size_t)lo * HH);
    const __nv_bfloat16* Al = (MODE == 0) ? g_Xl : (g_Hl + (size_t)lo * HH);
    const __nv_bfloat16* Bh = (MODE == 0) ? g_WxBh : g_WhBh;
    const __nv_bfloat16* Bl = (MODE == 0) ? g_WxBl : g_WhBl;
    float* Cout = ((MODE == 0) ? g_gx : g_YH) + (size_t)lo * GXC;

    unsigned sb = smem_u32(smem);
    int tid = threadIdx.x, lane = tid & 31, wid = tid >> 5;
    int m0w = (wid % WM) * MW, n0w = (wid / WM) * NW;
    int r16 = lane & 15, ahalf = lane >> 4;
    int rn  = (lane & 7) | ((lane >> 4) << 3);
    int kh  = (lane >> 3) & 1;
    int rg_ = lane >> 2, cg = (lane & 3) * 2;

    for (int tile = blockIdx.x; tile < ntiles; tile += GRID) {
        int cb0 = (tile & 7) * 128;
        int tm0 = (tile >> 3) * CTA_M;

        float acc[MF][NF][4];
#pragma unroll
        for (int a = 0; a < MF; a++)
#pragma unroll
            for (int b = 0; b < NF; b++)
#pragma unroll
                for (int c = 0; c < 4; c++) acc[a][b][c] = 0.0f;

        auto load_chunk = [&](int ch, int s) {
            int seg = ch / KC, kc = ch - seg * KC, k0 = kc * 64;
            const __nv_bfloat16* aseg = (seg == 1) ? Al : Ah;
            const __nv_bfloat16* bseg = (seg == 2) ? Bl : Bh;
            unsigned abase = sb + (unsigned)s * SS;
            unsigned bbase = abase + (unsigned)CTA_M * 128u;
#pragma unroll
            for (int i = 0; i < ITER; i++) {
                int u = tid + i * 256;
                if (u < ALINES) {
                    int row = u >> 3, c16 = u & 7;
                    int rg = tm0 + row;
                    if (rg >= M) rg = 0;                 // clamp: stay in level
                    cpa16(abase + sw128((unsigned)(row * 128 + c16 * 16)),
                          aseg + (size_t)rg * KEL + k0 + c16 * 8);
                } else {
                    int v = u - ALINES;
                    int row = v >> 3, c16 = v & 7;
                    cpa16(bbase + sw128((unsigned)(row * 128 + c16 * 16)),
                          bseg + (size_t)(cb0 + row) * KEL + k0 + c16 * 8);
                }
            }
            CP_COMMIT();
        };

        load_chunk(0, 0);
        load_chunk(1, 1);

        for (int ch = 0; ch < NCH; ch++) {
            if (ch + 1 < NCH) cp_wait<1>();   // chunk ch resident
            else              cp_wait<0>();
            __syncthreads();                  // compute(ch-1) done -> slot reusable
            if (ch + 2 < NCH) load_chunk(ch + 2, (ch + 2) % 3);

            unsigned sA = sb + (unsigned)(ch % 3) * SS;
            unsigned sB = sA + (unsigned)CTA_M * 128u;
#pragma unroll
            for (int ks = 0; ks < 4; ks++) {
                unsigned afr[MF][4];
#pragma unroll
                for (int mf = 0; mf < MF; mf++)
                    ldsm4(afr[mf], sA + sw128((unsigned)((m0w + mf * 16 + r16) * 128
                                                         + ks * 32 + ahalf * 16)));
                unsigned bfr[NF2][4];
#pragma unroll
                for (int nf2 = 0; nf2 < NF2; nf2++)
                    ldsm4(bfr[nf2], sB + sw128((unsigned)((n0w + nf2 * 16 + rn) * 128
                                                          + ks * 32 + kh * 16)));
#pragma unroll
                for (int mf = 0; mf < MF; mf++)
#pragma unroll
                    for (int nf = 0; nf < NF; nf++)
                        mma16816(acc[mf][nf], afr[mf],
                                 bfr[nf >> 1][(nf & 1) * 2],
                                 bfr[nf >> 1][(nf & 1) * 2 + 1]);
            }
        }
        __syncthreads();   // tile epilogue before next tile's loads reuse slots

#pragma unroll
        for (int mf = 0; mf < MF; mf++) {
#pragma unroll
            for (int hf = 0; hf < 2; hf++) {
                int rr = tm0 + m0w + mf * 16 + rg_ + hf * 8;
                if (rr < M) {
                    float* op = Cout + (size_t)rr * GXC;
#pragma unroll
                    for (int nf = 0; nf < NF; nf++) {
                        int col = cb0 + n0w + nf * 8 + cg;
                        float2 v;
                        v.x = acc[mf][nf][hf * 2];
                        v.y = acc[mf][nf][hf * 2 + 1];
                        if (MODE == 0) { v.x += g_bias[col]; v.y += g_bias[col + 1]; }
                        *(float2*)&op[col] = v;
                    }
                }
            }
        }
    }
}

// ---------------- leaf phase: gates only, bf16 split h ------------------------
__device__ void leaf_phase() {
    int t = threadIdx.x;
    for (int i = blockIdx.x; i < 6144; i += GRID) {
        int n = 2048 + i;
        const float* gx = g_gx + (size_t)n * GXC;
        float c = sigf(gx[t]) * tanhf(gx[768 + t]);
        float h = sigf(gx[512 + t]) * tanhf(c);
        g_C[n * HH + t] = c;
        split2(h, g_Hh[n * HH + t], g_Hl[n * HH + t]);
    }
}

// ---------------- internal-level ew phase -------------------------------------
// `ch < NN` guard is load-bearing: node 2047's 4th child index is 8192 == NN.
__device__ void ew_phase(int lo, int cnt) {
    int t = threadIdx.x;
    for (int i = blockIdx.x; i < cnt; i += GRID) {
        int n = lo + i;
        const float* gx = g_gx + (size_t)n * GXC;
        float ai = gx[t], af = gx[256 + t], ao = gx[512 + t], au = gx[768 + t];
        float fsum = 0.0f;
#pragma unroll
        for (int k = 0; k < 4; k++) {
            int ch = 4 * n + 1 + k;
            if (ch < NN) {
                const float* yh = g_YH + (size_t)ch * GXC;
                ai += yh[t];
                ao += yh[512 + t];
                au += yh[768 + t];
                fsum += sigf(af + yh[256 + t]) * g_C[ch * HH + t];
            }
        }
        float c = sigf(ai) * tanhf(au) + fsum;
        float h = sigf(ao) * tanhf(c);
        g_C[n * HH + t] = c;
        split2(h, g_Hh[n * HH + t], g_Hl[n * HH + t]);
    }
}

// ---------------- fused tiny level: gates + SIMT matvec YH --------------------
__device__ void fused_phase(float* hsm, int lo, int cnt) {
    int t = threadIdx.x;
    if (blockIdx.x < cnt) {
        int n = lo + blockIdx.x;
        const float* gx = g_gx + (size_t)n * GXC;
        float ai = gx[t], af = gx[256 + t], ao = gx[512 + t], au = gx[768 + t];
        float fsum = 0.0f;
#pragma unroll
        for (int k = 0; k < 4; k++) {
            int ch = 4 * n + 1 + k;
            const float* yh = g_YH + (size_t)ch * GXC;
            ai += yh[t];
            ao += yh[512 + t];
            au += yh[768 + t];
            fsum += sigf(af + yh[256 + t]) * g_C[ch * HH + t];
        }
        float c = sigf(ai) * tanhf(au) + fsum;
        float h = sigf(ao) * tanhf(c);
        g_C[n * HH + t] = c;
        hsm[t] = h;
        __syncthreads();
        float4 acc = make_float4(0.f, 0.f, 0.f, 0.f);
#pragma unroll 4
        for (int j = 0; j < HH; j++) {
            float hv = hsm[j];
            float4 w = *(const float4*)&g_WhT[j * GXC + 4 * t];
            acc.x = fmaf(w.x, hv, acc.x);
            acc.y = fmaf(w.y, hv, acc.y);
            acc.z = fmaf(w.z, hv, acc.z);
            acc.w = fmaf(w.w, hv, acc.w);
        }
        *(float4*)&g_YH[(size_t)n * GXC + 4 * t] = acc;
        __syncthreads();
    }
}

// ---------------- root gates + logits + log_softmax ---------------------------
__device__ void out_phase(float* h0, const float* Wout, const float* bout, float* out) {
    if (blockIdx.x != 0) return;
    __shared__ float logits[4];
    int t = threadIdx.x;
    const float* gx = g_gx;
    float ai = gx[t], af = gx[256 + t], ao = gx[512 + t], au = gx[768 + t];
    float fsum = 0.0f;
#pragma unroll
    for (int k = 0; k < 4; k++) {
        int ch = 1 + k;
        const float* yh = g_YH + (size_t)ch * GXC;
        ai += yh[t];
        ao += yh[512 + t];
        au += yh[768 + t];
        fsum += sigf(af + yh[256 + t]) * g_C[ch * HH + t];
    }
    float c = sigf(ai) * tanhf(au) + fsum;
    h0[t] = sigf(ao) * tanhf(c);
    __syncthreads();
    int w = t >> 5, lane = t & 31;
    if (w < 4) {
        float p = 0.0f;
        for (int j = lane; j < HH; j += 32) p += Wout[w * HH + j] * h0[j];
#pragma unroll
        for (int off = 16; off; off >>= 1) p += __shfl_down_sync(0xffffffffu, p, off);
        if (lane == 0) logits[w] = p + bout[w];
    }
    __syncthreads();
    if (t == 0) {
        float mx = fmaxf(fmaxf(logits[0], logits[1]), fmaxf(logits[2], logits[3]));
        float s = 0.0f;
#pragma unroll
        for (int o = 0; o < 4; o++) s += expf(logits[o] - mx);
        float lse = mx + logf(s);
#pragma unroll
        for (int o = 0; o < 4; o++) out[o] = logits[o] - lse;
    }
}

// ---------------- mega kernel: everything after prep --------------------------
__global__ __launch_bounds__(256, 2)
void mega_kernel(const float* __restrict__ Wout, const float* __restrict__ bout,
                 float* __restrict__ out) {
    extern __shared__ __align__(1024) char smem[];   // 96KB: GEMM stages / hsm
    float* hsm = (float*)smem;

    // gx = X @ Wx^T + bias   [512 tiles, 128x128, 4x2 warps]
    gemm_phase<0, 128, 4, 2>(smem, 0, NN, 512);
    gsync();
    leaf_phase();
    gsync();
    // leaf YH [384 tiles]
    gemm_phase<1, 128, 4, 2>(smem, 2048, 6144, 384);
    gsync();
    ew_phase(1365, 683);
    gsync();
    gemm_phase<1, 64, 2, 4>(smem, 1365, 683, 88);    // 11 row-tiles x 8
    gsync();
    ew_phase(341, 1024);
    gsync();
    gemm_phase<1, 64, 2, 4>(smem, 341, 1024, 128);   // 16 x 8
    gsync();
    ew_phase(85, 256);
    gsync();
    gemm_phase<1, 64, 2, 4>(smem, 85, 256, 32);      // 4 x 8
    gsync();
    fused_phase(hsm, 21, 64);
    gsync();
    fused_phase(hsm, 5, 16);
    gsync();
    fused_phase(hsm, 1, 4);
    gsync();
    out_phase(hsm, Wout, bout, out);
}

// ---------------- launch ------------------------------------------------------
#define SMEM_MEGA 98304   // 3 x (128+128)*128

extern "C" void kernel_launch(void* const* d_in, const int* in_sizes, int n_in,
                              void* d_out, int out_size) {
    const int*   xs   = (const int*)  d_in[0];
    const float* emb  = (const float*)d_in[3];
    const float* Wx   = (const float*)d_in[4];
    const float* bx   = (const float*)d_in[5];
    const float* Wh   = (const float*)d_in[6];
    const float* bh   = (const float*)d_in[7];
    const float* Wout = (const float*)d_in[8];
    const float* bout = (const float*)d_in[9];
    float* out = (float*)d_out;

    cudaFuncSetAttribute(mega_kernel, cudaFuncAttributeMaxDynamicSharedMemorySize, SMEM_MEGA);

    // 1) pack weights + split gathered embeddings
    prep_kernel<<<1280 + (NN * KPX) / 256, 256>>>(Wx, bx, Wh, bh, xs, emb);

    // 2) everything else in one persistent launch (backoff grid barriers)
    mega_kernel<<<GRID, 256, SMEM_MEGA>>>(Wout, bout, out);
}

// round 17
// speedup vs baseline: 1.3848x; 1.3848x over previous
#include <cuda_runtime.h>
#include <cuda_bf16.h>
#include <math.h>

#define NN   8192
#define HH   256
#define DD   300
#define GXC  1024
#define KPX  320    // D padded to 64-multiple

// ---------------- scratch -----------------------------------------------------
__device__ __align__(256) float         g_gx [NN * GXC];
__device__ __align__(256) float         g_YH [NN * GXC];
__device__ __align__(256) float         g_C  [NN * HH];
__device__ __align__(256) __nv_bfloat16 g_Hh [NN * HH];    // bf16 split h
__device__ __align__(256) __nv_bfloat16 g_Hl [NN * HH];
__device__ __align__(256) __nv_bfloat16 g_Xh [NN * KPX];
__device__ __align__(256) __nv_bfloat16 g_Xl [NN * KPX];
__device__ __align__(256) __nv_bfloat16 g_WxBh[GXC * KPX];
__device__ __align__(256) __nv_bfloat16 g_WxBl[GXC * KPX];
__device__ __align__(256) __nv_bfloat16 g_WhBh[GXC * HH];
__device__ __align__(256) __nv_bfloat16 g_WhBl[GXC * HH];
__device__ __align__(256) float         g_WhT [HH * GXC];   // [j][m] for fused matvec
__device__ __align__(256) float         g_bias[GXC];

__device__ __forceinline__ float sigf(float x) { return 1.0f / (1.0f + expf(-x)); }

__device__ __forceinline__ void split2(float v, __nv_bfloat16& h, __nv_bfloat16& l) {
    h = __float2bfloat16_rn(v);
    l = __float2bfloat16_rn(v - __bfloat162float(h));
}

// ---------------- generic-PTX tensor helpers ----------------------------------
__device__ __forceinline__ unsigned smem_u32(const void* p) {
    unsigned a;
    asm("{ .reg .u64 t; cvta.to.shared.u64 t, %1; cvt.u32.u64 %0, t; }"
        : "=r"(a) : "l"(p));
    return a;
}
// SW64 swizzle for 64-byte rows (8-row x 64B atom) — conflict-free for
// ldmatrix 8x16B column reads and for 16B cp.async stores.
__device__ __forceinline__ unsigned sw64(unsigned x) { return x ^ ((x >> 3) & 0x30); }

__device__ __forceinline__ void cpa16(unsigned d, const void* s) {
    asm volatile("cp.async.cg.shared.global [%0], [%1], 16;" :: "r"(d), "l"(s));
}
#define CP_COMMIT() asm volatile("cp.async.commit_group;" ::: "memory")
template <int N> __device__ __forceinline__ void cp_wait() {
    asm volatile("cp.async.wait_group %0;" :: "n"(N) : "memory");
}

__device__ __forceinline__ void ldsm4(unsigned* r, unsigned addr) {
    asm volatile("ldmatrix.sync.aligned.m8n8.x4.shared.b16 {%0,%1,%2,%3}, [%4];"
                 : "=r"(r[0]), "=r"(r[1]), "=r"(r[2]), "=r"(r[3]) : "r"(addr));
}

__device__ __forceinline__ void mma16816(float* c, const unsigned* a,
                                         unsigned b0, unsigned b1) {
    asm volatile(
        "mma.sync.aligned.m16n8k16.row.col.f32.bf16.bf16.f32 "
        "{%0,%1,%2,%3}, {%4,%5,%6,%7}, {%8,%9}, {%0,%1,%2,%3};"
        : "+f"(c[0]), "+f"(c[1]), "+f"(c[2]), "+f"(c[3])
        : "r"(a[0]), "r"(a[1]), "r"(a[2]), "r"(a[3]), "r"(b0), "r"(b1));
}

// ---------------- prep: weight pack + bias + embedding gather/split -----------
__global__ void prep_kernel(const float* __restrict__ Wx, const float* __restrict__ bx,
                            const float* __restrict__ Wh, const float* __restrict__ bh,
                            const int*   __restrict__ xs, const float* __restrict__ emb) {
    int b = blockIdx.x, t = threadIdx.x;
    if (b < 1280) {
        int i = b * 256 + t;
        if (i < GXC * KPX) {
            int m = i / KPX, k = i - m * KPX;
            float v = (k < DD) ? Wx[m * DD + k] : 0.0f;
            split2(v, g_WxBh[i], g_WxBl[i]);
        }
        if (i < GXC * HH) {
            float v = Wh[i];                       // i = m*256 + j (K-contig)
            split2(v, g_WhBh[i], g_WhBl[i]);
            int m = i >> 8, j = i & 255;
            g_WhT[j * GXC + m] = v;
        }
        if (i < GXC) g_bias[i] = bx[i] + bh[i];
    } else {
        int j = (b - 1280) * 256 + t;              // [0, NN*KPX)
        int n = j / KPX, k = j - n * KPX;
        float v = (k < DD) ? emb[(size_t)xs[n] * DD + k] : 0.0f;
        split2(v, g_Xh[j], g_Xl[j]);
    }
}

// ---------------- HMMA GEMM: fused split-bf16, K-chunk 32, 3-stage ------------
// MODE 0: g_gx = g_X @ g_WxB^T + bias   (K=320)
// MODE 1: g_YH[lo..] = bf16-split H[lo..] @ g_WhB^T (K=256)
// Each 32-K stage holds Ah | Al | Bh | Bl sub-tiles (64B rows, SW64 swizzle).
// Per k16 step: 12 LDSM.x4 feed 3 MMA sets (hh, lh, hl) — 33% less shared
// traffic than the 3-sequential-segment scheme.
// Warp grid WM x WN over CTA_M x 128.
template <int MODE, int CTA_M, int WM, int WN>
__global__ __launch_bounds__(256, 2)
void gemm_t(int lo, int M) {
    constexpr int KEL = (MODE == 0) ? KPX : HH;
    constexpr int NCH = KEL / 32;                  // 32-wide K chunks
    constexpr int MW  = CTA_M / WM, NW = 128 / WN;
    constexpr int MF  = MW / 16, NF = NW / 8, NF2 = NW / 16;
    constexpr int AL  = CTA_M * 4;                 // 16B lines per A sub-tile
    constexpr int BL  = 128 * 4;                   // per B sub-tile
    constexpr int TOTL = 2 * AL + 2 * BL;
    constexpr int ITER = TOTL / 256;
    constexpr unsigned SS = (unsigned)TOTL * 16u;  // stage bytes
    constexpr unsigned O_AL = (unsigned)CTA_M * 64u;
    constexpr unsigned O_BH = 2u * O_AL;
    constexpr unsigned O_BL = O_BH + 8192u;

    const __nv_bfloat16* Ah = (MODE == 0) ? g_Xh : (g_Hh + (size_t)lo * HH);
    const __nv_bfloat16* Al = (MODE == 0) ? g_Xl : (g_Hl + (size_t)lo * HH);
    const __nv_bfloat16* Bh = (MODE == 0) ? g_WxBh : g_WhBh;
    const __nv_bfloat16* Bl = (MODE == 0) ? g_WxBl : g_WhBl;
    float* Cout = ((MODE == 0) ? g_gx : g_YH) + (size_t)lo * GXC;

    extern __shared__ __align__(1024) char smem[];
    unsigned sb = smem_u32(smem);
    int tid = threadIdx.x, lane = tid & 31, wid = tid >> 5;
    int tm0 = blockIdx.y * CTA_M;
    int cb0 = blockIdx.x * 128;
    int m0w = (wid % WM) * MW, n0w = (wid / WM) * NW;

    float acc[MF][NF][4];
#pragma unroll
    for (int a = 0; a < MF; a++)
#pragma unroll
        for (int b = 0; b < NF; b++)
#pragma unroll
            for (int c = 0; c < 4; c++) acc[a][b][c] = 0.0f;

    auto load_chunk = [&](int ch, int s) {
        int k0 = ch * 32;
        unsigned base = sb + (unsigned)s * SS;
#pragma unroll
        for (int i = 0; i < ITER; i++) {
            int u = tid + i * 256;
            const __nv_bfloat16* src;
            unsigned dst;
            int row, c16;
            if (u < AL) {
                row = u >> 2; c16 = u & 3;
                int rg = tm0 + row; if (rg >= M) rg = 0;
                src = Ah + (size_t)rg * KEL + k0 + c16 * 8;
                dst = base + sw64((unsigned)(row * 64 + c16 * 16));
            } else if (u < 2 * AL) {
                int v = u - AL; row = v >> 2; c16 = v & 3;
                int rg = tm0 + row; if (rg >= M) rg = 0;
                src = Al + (size_t)rg * KEL + k0 + c16 * 8;
                dst = base + O_AL + sw64((unsigned)(row * 64 + c16 * 16));
            } else if (u < 2 * AL + BL) {
                int v = u - 2 * AL; row = v >> 2; c16 = v & 3;
                src = Bh + (size_t)(cb0 + row) * KEL + k0 + c16 * 8;
                dst = base + O_BH + sw64((unsigned)(row * 64 + c16 * 16));
            } else {
                int v = u - 2 * AL - BL; row = v >> 2; c16 = v & 3;
                src = Bl + (size_t)(cb0 + row) * KEL + k0 + c16 * 8;
                dst = base + O_BL + sw64((unsigned)(row * 64 + c16 * 16));
            }
            cpa16(dst, src);
        }
        CP_COMMIT();
    };

    // prologue: stage chunks 0 and 1
    load_chunk(0, 0);
    load_chunk(1, 1);

    int r16 = lane & 15, ahalf = lane >> 4;
    int rn  = (lane & 7) | ((lane >> 4) << 3);
    int kh  = (lane >> 3) & 1;

    for (int ch = 0; ch < NCH; ch++) {
        if (ch + 1 < NCH) cp_wait<1>();   // chunk ch resident
        else              cp_wait<0>();
        __syncthreads();                  // compute(ch-1) done -> slot reusable
        if (ch + 2 < NCH) load_chunk(ch + 2, (ch + 2) % 3);

        unsigned base = sb + (unsigned)(ch % 3) * SS;
#pragma unroll
        for (int ks = 0; ks < 2; ks++) {
            unsigned afh[MF][4], afl[MF][4];
#pragma unroll
            for (int mf = 0; mf < MF; mf++) {
                unsigned off = sw64((unsigned)((m0w + mf * 16 + r16) * 64
                                               + ks * 32 + ahalf * 16));
                ldsm4(afh[mf], base + off);
                ldsm4(afl[mf], base + O_AL + off);
            }
            unsigned bfh[NF2][4], bfl[NF2][4];
#pragma unroll
            for (int nf2 = 0; nf2 < NF2; nf2++) {
                unsigned off = sw64((unsigned)((n0w + nf2 * 16 + rn) * 64
                                               + ks * 32 + kh * 16));
                ldsm4(bfh[nf2], base + O_BH + off);
                ldsm4(bfl[nf2], base + O_BL + off);
            }
            // hh
#pragma unroll
            for (int mf = 0; mf < MF; mf++)
#pragma unroll
                for (int nf = 0; nf < NF; nf++)
                    mma16816(acc[mf][nf], afh[mf],
                             bfh[nf >> 1][(nf & 1) * 2],
                             bfh[nf >> 1][(nf & 1) * 2 + 1]);
            // lh
#pragma unroll
            for (int mf = 0; mf < MF; mf++)
#pragma unroll
                for (int nf = 0; nf < NF; nf++)
                    mma16816(acc[mf][nf], afl[mf],
                             bfh[nf >> 1][(nf & 1) * 2],
                             bfh[nf >> 1][(nf & 1) * 2 + 1]);
            // hl
#pragma unroll
            for (int mf = 0; mf < MF; mf++)
#pragma unroll
                for (int nf = 0; nf < NF; nf++)
                    mma16816(acc[mf][nf], afh[mf],
                             bfl[nf >> 1][(nf & 1) * 2],
                             bfl[nf >> 1][(nf & 1) * 2 + 1]);
        }
    }

    int rg = lane >> 2, cg = (lane & 3) * 2;
#pragma unroll
    for (int mf = 0; mf < MF; mf++) {
#pragma unroll
        for (int hf = 0; hf < 2; hf++) {
            int rr = tm0 + m0w + mf * 16 + rg + hf * 8;
            if (rr < M) {
                float* op = Cout + (size_t)rr * GXC;
#pragma unroll
                for (int nf = 0; nf < NF; nf++) {
                    int col = cb0 + n0w + nf * 8 + cg;
                    float2 v;
                    v.x = acc[mf][nf][hf * 2];
                    v.y = acc[mf][nf][hf * 2 + 1];
                    if (MODE == 0) { v.x += g_bias[col]; v.y += g_bias[col + 1]; }
                    *(float2*)&op[col] = v;
                }
            }
        }
    }
}

// ---------------- leaves: gates only, bf16 split h ----------------------------
__global__ void leaf_ew() {
    int n = 2048 + blockIdx.x;
    int t = threadIdx.x;
    const float* gx = g_gx + (size_t)n * GXC;
    float c = sigf(gx[t]) * tanhf(gx[768 + t]);
    float h = sigf(gx[512 + t]) * tanhf(c);
    g_C[n * HH + t] = c;
    split2(h, g_Hh[n * HH + t], g_Hl[n * HH + t]);
}

// ---------------- internal level: gather children YH + gates ------------------
// `ch < NN` guard is load-bearing: node 2047's 4th child index is 8192 == NN.
__global__ void level_ew(int lo) {
    int n = lo + blockIdx.x;
    int t = threadIdx.x;
    const float* gx = g_gx + (size_t)n * GXC;
    float ai = gx[t], af = gx[256 + t], ao = gx[512 + t], au = gx[768 + t];
    float fsum = 0.0f;
#pragma unroll
    for (int k = 0; k < 4; k++) {
        int ch = 4 * n + 1 + k;
        if (ch < NN) {
            const float* yh = g_YH + (size_t)ch * GXC;
            ai += yh[t];
            ao += yh[512 + t];
            au += yh[768 + t];
            fsum += sigf(af + yh[256 + t]) * g_C[ch * HH + t];
        }
    }
    float c = sigf(ai) * tanhf(au) + fsum;
    float h = sigf(ao) * tanhf(c);
    g_C[n * HH + t] = c;
    split2(h, g_Hh[n * HH + t], g_Hl[n * HH + t]);
}

// ---------------- fused tiny level: gates + SIMT matvec YH --------------------
__global__ void fused_level(int lo) {
    __shared__ float hsm[HH];
    int n = lo + blockIdx.x;
    int t = threadIdx.x;
    const float* gx = g_gx + (size_t)n * GXC;
    float ai = gx[t], af = gx[256 + t], ao = gx[512 + t], au = gx[768 + t];
    float fsum = 0.0f;
#pragma unroll
    for (int k = 0; k < 4; k++) {
        int ch = 4 * n + 1 + k;
        const float* yh = g_YH + (size_t)ch * GXC;
        ai += yh[t];
        ao += yh[512 + t];
        au += yh[768 + t];
        fsum += sigf(af + yh[256 + t]) * g_C[ch * HH + t];
    }
    float c = sigf(ai) * tanhf(au) + fsum;
    float h = sigf(ao) * tanhf(c);
    g_C[n * HH + t] = c;
    hsm[t] = h;
    __syncthreads();
    float4 acc = make_float4(0.f, 0.f, 0.f, 0.f);
#pragma unroll 4
    for (int j = 0; j < HH; j++) {
        float hv = hsm[j];
        float4 w = *(const float4*)&g_WhT[j * GXC + 4 * t];
        acc.x = fmaf(w.x, hv, acc.x);
        acc.y = fmaf(w.y, hv, acc.y);
        acc.z = fmaf(w.z, hv, acc.z);
        acc.w = fmaf(w.w, hv, acc.w);
    }
    *(float4*)&g_YH[(size_t)n * GXC + 4 * t] = acc;
}

// ---------------- root gates + logits + log_softmax ---------------------------
__global__ void out_kernel(const float* __restrict__ Wout,
                           const float* __restrict__ bout,
                           float* __restrict__ out) {
    __shared__ float h0[HH];
    __shared__ float logits[4];
    int t = threadIdx.x;
    const float* gx = g_gx;
    float ai = gx[t], af = gx[256 + t], ao = gx[512 + t], au = gx[768 + t];
    float fsum = 0.0f;
#pragma unroll
    for (int k = 0; k < 4; k++) {
        int ch = 1 + k;
        const float* yh = g_YH + (size_t)ch * GXC;
        ai += yh[t];
        ao += yh[512 + t];
        au += yh[768 + t];
        fsum += sigf(af + yh[256 + t]) * g_C[ch * HH + t];
    }
    float c = sigf(ai) * tanhf(au) + fsum;
    h0[t] = sigf(ao) * tanhf(c);
    __syncthreads();
    int w = t >> 5, lane = t & 31;
    if (w < 4) {
        float p = 0.0f;
        for (int j = lane; j < HH; j += 32) p += Wout[w * HH + j] * h0[j];
#pragma unroll
        for (int off = 16; off; off >>= 1) p += __shfl_down_sync(0xffffffffu, p, off);
        if (lane == 0) logits[w] = p + bout[w];
    }
    __syncthreads();
    if (t == 0) {
        float mx = fmaxf(fmaxf(logits[0], logits[1]), fmaxf(logits[2], logits[3]));
        float s = 0.0f;
#pragma unroll
        for (int o = 0; o < 4; o++) s += expf(logits[o] - mx);
        float lse = mx + logf(s);
#pragma unroll
        for (int o = 0; o < 4; o++) out[o] = logits[o] - lse;
    }
}

// ---------------- launch ------------------------------------------------------
#define SMEM_BIG 98304    // 3 x (2*128 + 2*128)*64  = 3 x 32KB
#define SMEM_MID 73728    // 3 x (2*64 + 2*128)*64   = 3 x 24KB

#define GEMM_BIG0 gemm_t<0, 128, 4, 2>
#define GEMM_BIG1 gemm_t<1, 128, 4, 2>
#define GEMM_MID1 gemm_t<1, 64, 2, 4>

extern "C" void kernel_launch(void* const* d_in, const int* in_sizes, int n_in,
                              void* d_out, int out_size) {
    const int*   xs   = (const int*)  d_in[0];
    const float* emb  = (const float*)d_in[3];
    const float* Wx   = (const float*)d_in[4];
    const float* bx   = (const float*)d_in[5];
    const float* Wh   = (const float*)d_in[6];
    const float* bh   = (const float*)d_in[7];
    const float* Wout = (const float*)d_in[8];
    const float* bout = (const float*)d_in[9];
    float* out = (float*)d_out;

    cudaFuncSetAttribute(GEMM_BIG0, cudaFuncAttributeMaxDynamicSharedMemorySize, SMEM_BIG);
    cudaFuncSetAttribute(GEMM_BIG1, cudaFuncAttributeMaxDynamicSharedMemorySize, SMEM_BIG);
    cudaFuncSetAttribute(GEMM_MID1, cudaFuncAttributeMaxDynamicSharedMemorySize, SMEM_MID);

    // 1) pack weights + split gathered embeddings (one launch)
    prep_kernel<<<1280 + (NN * KPX) / 256, 256>>>(Wx, bx, Wh, bh, xs, emb);

    // 2) gx = X @ Wx^T + (bx+bh)   [fused split-bf16 HMMA]
    GEMM_BIG0<<<dim3(8, 64), 256, SMEM_BIG>>>(0, NN);

    // 3) leaves: gates, then YH GEMM
    leaf_ew<<<6144, 256>>>();
    GEMM_BIG1<<<dim3(8, 48), 256, SMEM_BIG>>>(2048, 6144);

    // 4) internal levels bottom-up: mid levels 64x128, tiny levels fused
    level_ew<<<683, 256>>>(1365);  GEMM_MID1<<<dim3(8, 11), 256, SMEM_MID>>>(1365, 683);
    level_ew<<<1024, 256>>>(341);  GEMM_MID1<<<dim3(8, 16), 256, SMEM_MID>>>(341, 1024);
    level_ew<<<256, 256>>>(85);    GEMM_MID1<<<dim3(8, 4), 256, SMEM_MID>>>(85, 256);
    fused_level<<<64, 256>>>(21);
    fused_level<<<16, 256>>>(5);
    fused_level<<<4, 256>>>(1);

    // 5) root output + log_softmax
    out_kernel<<<1, 256>>>(Wout, bout, out);
}